// round 8
// baseline (speedup 1.0000x reference)
#include <cuda_runtime.h>

#define NB 8
#define PP 2048
#define DD 64
#define EPSI 1e-3f
#define KK 1442.69504089f        /* 1000 * log2(e) */
#define EL2 6.9314718056e-4f     /* ln2 / 1000 */
#define NPb (NB*PP)
#define NITER 10

__device__ __align__(256) float g_C[(size_t)NB * PP * PP]; // 134 MB cost matrix
__device__ __align__(256) float g_An[NPb * DD];
__device__ __align__(256) float g_Bn[NPb * DD];
__device__ __align__(256) float g_rs[NPb];
__device__ __align__(256) float g_cs[NPb];
__device__ __align__(256) float g_lmu[NPb];
__device__ __align__(256) float g_lnu[NPb];
__device__ __align__(256) float g_u[NPb];
__device__ __align__(256) float g_v[NPb];
__device__ __align__(256) float g_pm[NB * 16 * PP];       // col partial max (log2)
__device__ __align__(256) float g_ps[NB * 16 * PP];       // col partial sum
__device__ __align__(256) float g_usnap[NITER * NPb];     // u after body it
__device__ __align__(256) float g_vsnap[NITER * NPb];     // v after body it
__device__ float g_errsum[16];
__device__ int g_kstar;

// ---------------- block sum reduction (256 threads) ------------------------
__device__ __forceinline__ float block_sum256(float v, float* red) {
    __syncthreads();
    #pragma unroll
    for (int off = 16; off; off >>= 1) v += __shfl_xor_sync(0xffffffffu, v, off);
    int w = threadIdx.x >> 5, l = threadIdx.x & 31;
    if (l == 0) red[w] = v;
    __syncthreads();
    if (threadIdx.x < 32) {
        float x = (l < 8) ? red[l] : 0.0f;
        #pragma unroll
        for (int off = 4; off; off >>= 1) x += __shfl_xor_sync(0xffffffffu, x, off);
        if (l == 0) red[32] = x;
    }
    __syncthreads();
    return red[32];
}

// ---------------- prep: normalize inputs, zero state -----------------------
__global__ __launch_bounds__(256) void k_prep(const float* __restrict__ a,
                                              const float* __restrict__ b,
                                              float* __restrict__ out) {
    int idx = blockIdx.x * 256 + threadIdx.x;          // 0..16383
    {
        const float4* s = (const float4*)(a + (size_t)idx * DD);
        float nrm = 0.0f;
        #pragma unroll
        for (int q = 0; q < 16; q++) {
            float4 t = s[q];
            nrm += t.x * t.x + t.y * t.y + t.z * t.z + t.w * t.w;
        }
        float sc = 1.0f / fmaxf(sqrtf(nrm), 1e-12f);
        float4* d = (float4*)(g_An + (size_t)idx * DD);
        #pragma unroll
        for (int q = 0; q < 16; q++) {
            float4 t = s[q];
            t.x *= sc; t.y *= sc; t.z *= sc; t.w *= sc;
            d[q] = t;
        }
    }
    {
        const float4* s = (const float4*)(b + (size_t)idx * DD);
        float nrm = 0.0f;
        #pragma unroll
        for (int q = 0; q < 16; q++) {
            float4 t = s[q];
            nrm += t.x * t.x + t.y * t.y + t.z * t.z + t.w * t.w;
        }
        float sc = 1.0f / fmaxf(sqrtf(nrm), 1e-12f);
        float4* d = (float4*)(g_Bn + (size_t)idx * DD);
        #pragma unroll
        for (int q = 0; q < 16; q++) {
            float4 t = s[q];
            t.x *= sc; t.y *= sc; t.z *= sc; t.w *= sc;
            d[q] = t;
        }
    }
    g_u[idx] = 0.0f; g_v[idx] = 0.0f; g_rs[idx] = 0.0f; g_cs[idx] = 0.0f;
    if (idx < NB) out[idx] = 0.0f;
    if (idx < 16) g_errsum[idx] = 0.0f;
    if (idx == 0) g_kstar = NITER - 1;
}

// ------- GEMM over 4 batches: C = 1 - Ahat . Bhat^T, fused S sums ---------
__global__ __launch_bounds__(256) void k_gemm(int b0) {
    __shared__ float As[128][33];
    __shared__ float Bs[32][132];
    int b = b0 + blockIdx.z;
    int row0 = blockIdx.y * 128, col0 = blockIdx.x * 128;
    const float* Ab = g_An + (size_t)b * PP * DD;
    const float* Bb = g_Bn + (size_t)b * PP * DD;
    int t = threadIdx.x, tx = t & 15, ty = t >> 4;

    unsigned long long acc[8][4];
    #pragma unroll
    for (int i = 0; i < 8; i++)
        #pragma unroll
        for (int j = 0; j < 4; j++) acc[i][j] = 0ULL;

    #pragma unroll
    for (int kp = 0; kp < 2; kp++) {
        __syncthreads();
        int kq = t & 7, rq = t >> 3;
        #pragma unroll
        for (int p = 0; p < 4; p++) {
            int r = p * 32 + rq;
            float4 v = *(const float4*)(Ab + (size_t)(row0 + r) * DD + kp * 32 + kq * 4);
            As[r][kq * 4 + 0] = v.x; As[r][kq * 4 + 1] = v.y;
            As[r][kq * 4 + 2] = v.z; As[r][kq * 4 + 3] = v.w;
            float4 w = *(const float4*)(Bb + (size_t)(col0 + r) * DD + kp * 32 + kq * 4);
            Bs[kq * 4 + 0][r] = w.x; Bs[kq * 4 + 1][r] = w.y;
            Bs[kq * 4 + 2][r] = w.z; Bs[kq * 4 + 3][r] = w.w;
        }
        __syncthreads();
        #pragma unroll 4
        for (int k = 0; k < 32; k++) {
            union { float4 f; unsigned long long u[2]; } b0u, b1u;
            b0u.f = *(const float4*)&Bs[k][tx * 4];
            b1u.f = *(const float4*)&Bs[k][64 + tx * 4];
            #pragma unroll
            for (int i = 0; i < 8; i++) {
                unsigned int ai = __float_as_uint(As[ty * 8 + i][k]);
                unsigned long long a2;
                asm("mov.b64 %0, {%1, %1};" : "=l"(a2) : "r"(ai));
                asm("fma.rn.f32x2 %0, %1, %2, %0;" : "+l"(acc[i][0]) : "l"(a2), "l"(b0u.u[0]));
                asm("fma.rn.f32x2 %0, %1, %2, %0;" : "+l"(acc[i][1]) : "l"(a2), "l"(b0u.u[1]));
                asm("fma.rn.f32x2 %0, %1, %2, %0;" : "+l"(acc[i][2]) : "l"(a2), "l"(b1u.u[0]));
                asm("fma.rn.f32x2 %0, %1, %2, %0;" : "+l"(acc[i][3]) : "l"(a2), "l"(b1u.u[1]));
            }
        }
    }
    __syncthreads();

    float rs[8], cs8[8];
    #pragma unroll
    for (int j = 0; j < 8; j++) cs8[j] = 0.0f;
    #pragma unroll
    for (int i = 0; i < 8; i++) {
        float vals[8];
        #pragma unroll
        for (int jp = 0; jp < 4; jp++) {
            union { unsigned long long u; float2 f; } cv; cv.u = acc[i][jp];
            vals[jp * 2 + 0] = cv.f.x;
            vals[jp * 2 + 1] = cv.f.y;
        }
        size_t base = ((size_t)b * PP + row0 + ty * 8 + i) * (size_t)PP + col0;
        *(float4*)(g_C + base + tx * 4) =
            make_float4(1.0f - vals[0], 1.0f - vals[1], 1.0f - vals[2], 1.0f - vals[3]);
        *(float4*)(g_C + base + 64 + tx * 4) =
            make_float4(1.0f - vals[4], 1.0f - vals[5], 1.0f - vals[6], 1.0f - vals[7]);
        float rsum = 0.0f;
        #pragma unroll
        for (int j = 0; j < 8; j++) { rsum += vals[j]; cs8[j] += vals[j]; }
        rs[i] = rsum;
    }
    float* red = (float*)As;
    #pragma unroll
    for (int i = 0; i < 8; i++) red[(ty * 8 + i) * 16 + tx] = rs[i];
    __syncthreads();
    if (t < 128) {
        float s = 0.0f;
        #pragma unroll
        for (int q = 0; q < 16; q++) s += red[t * 16 + q];
        atomicAdd(&g_rs[b * PP + row0 + t], s);
    }
    __syncthreads();
    #pragma unroll
    for (int j = 0; j < 8; j++) {
        int cc = (j < 4) ? (tx * 4 + j) : (64 + tx * 4 + (j - 4));
        red[cc * 16 + ty] = cs8[j];
    }
    __syncthreads();
    if (t < 128) {
        float s = 0.0f;
        #pragma unroll
        for (int q = 0; q < 16; q++) s += red[t * 16 + q];
        atomicAdd(&g_cs[b * PP + col0 + t], s);
    }
}

// ---------------- weights -> log(mu+1e-8) ----------------------------------
__device__ __forceinline__ void wproc(const float* __restrict__ sum,
                                      float* __restrict__ out, float* red, int t) {
    float raw[8], s = 0.0f;
    #pragma unroll
    for (int q = 0; q < 8; q++) {
        raw[q] = sum[t + 256 * q] * (1.0f / PP);
        s += fabsf(raw[q]);
    }
    s = block_sum256(s, red);
    float inv1 = 1.0f / fmaxf(s, 1e-12f);
    float c[8]; float s2 = 0.0f;
    #pragma unroll
    for (int q = 0; q < 8; q++) { c[q] = fmaxf(raw[q] * inv1, 0.0f); s2 += fabsf(c[q]); }
    s2 = block_sum256(s2, red);
    float inv2 = 1.0f / fmaxf(s2, 1e-12f);
    #pragma unroll
    for (int q = 0; q < 8; q++) out[t + 256 * q] = logf(c[q] * inv2 + 1e-8f);
}

__global__ __launch_bounds__(256) void k_weights(int b0) {
    __shared__ float red[40];
    int b = b0 + blockIdx.x, t = threadIdx.x;
    wproc(g_rs + b * PP, g_lmu + b * PP, red, t);
    wproc(g_cs + b * PP, g_lnu + b * PP, red, t);
}

// ---- row pass (group of 4, REVERSE sweep): quarter-row/warp, 2 rows/block -
__global__ __launch_bounds__(256) void k_row(int b0, int it) {
    __shared__ float vs[2048];          // v * KK
    __shared__ float wm[8], ws[8];
    __shared__ float erw[2];
    int t = threadIdx.x, l = t & 31, w = t >> 5;
    int rev = 4095 - blockIdx.x;        // serpentine within group
    int b = b0 + (rev >> 10);
    const float4* vsrc = (const float4*)(g_v + (b << 11));
    #pragma unroll
    for (int q = 0; q < 2; q++) {
        float4 v4 = vsrc[t + q * 256];
        ((float4*)vs)[t + q * 256] = make_float4(v4.x * KK, v4.y * KK, v4.z * KK, v4.w * KK);
    }
    __syncthreads();
    int row2 = (rev & 1023) << 1;
    int rl = w >> 2, qq = w & 3;        // row-in-block, quarter
    int bi = (b << 11) + row2 + rl;
    const float* Crow = g_C + ((size_t)bi << 11) + (qq << 9);
    const float* vh = vs + (qq << 9);

    float x[16];
    #pragma unroll
    for (int k = 0; k < 4; k++) {
        float4 c = *(const float4*)(Crow + k * 128 + l * 4);
        float4 vv = *(const float4*)(vh + k * 128 + l * 4);
        x[k * 4 + 0] = fmaf(c.x, -KK, vv.x);
        x[k * 4 + 1] = fmaf(c.y, -KK, vv.y);
        x[k * 4 + 2] = fmaf(c.z, -KK, vv.z);
        x[k * 4 + 3] = fmaf(c.w, -KK, vv.w);
    }
    float mk[4];
    #pragma unroll
    for (int k = 0; k < 4; k++)
        mk[k] = fmaxf(fmaxf(x[k*4], x[k*4+1]), fmaxf(x[k*4+2], x[k*4+3]));
    float m = fmaxf(fmaxf(mk[0], mk[1]), fmaxf(mk[2], mk[3]));
    #pragma unroll
    for (int off = 16; off; off >>= 1) m = fmaxf(m, __shfl_xor_sync(0xffffffffu, m, off));
    float s0 = 0.0f, s1 = 0.0f, s2 = 0.0f, s3 = 0.0f;
    #pragma unroll
    for (int k = 0; k < 4; k++) {
        s0 += exp2f(x[k * 4 + 0] - m);
        s1 += exp2f(x[k * 4 + 1] - m);
        s2 += exp2f(x[k * 4 + 2] - m);
        s3 += exp2f(x[k * 4 + 3] - m);
    }
    float s = (s0 + s1) + (s2 + s3);
    #pragma unroll
    for (int off = 16; off; off >>= 1) s += __shfl_xor_sync(0xffffffffu, s, off);
    if (l == 0) { wm[w] = m; ws[w] = s; }
    __syncthreads();
    if (t < 2) {
        float M = fmaxf(fmaxf(wm[t*4], wm[t*4+1]), fmaxf(wm[t*4+2], wm[t*4+3]));
        float S = ws[t*4]   * exp2f(wm[t*4]   - M) + ws[t*4+1] * exp2f(wm[t*4+1] - M)
                + ws[t*4+2] * exp2f(wm[t*4+2] - M) + ws[t*4+3] * exp2f(wm[t*4+3] - M);
        int bi2 = (b << 11) + row2 + t;
        float un = EPSI * g_lmu[bi2] - EL2 * (M + __log2f(S));
        erw[t] = fabsf(un - g_u[bi2]);
        g_u[bi2] = un;
    }
    __syncthreads();
    if (t == 0) atomicAdd(&g_errsum[it], erw[0] + erw[1]);
}

// ---- col pass partials (group of 4, FORWARD sweep) ------------------------
__global__ __launch_bounds__(256) void k_col(int b0) {
    __shared__ float us[128];           // u * KK
    int blk = blockIdx.x;               // 512 = b(4) x chunk(16) x tile(8)
    int b = b0 + (blk >> 7);
    int chunk = (blk >> 3) & 15;
    int tile = blk & 7;
    int t = threadIdx.x;
    int j = (tile << 8) + t;
    int r0 = chunk << 7;
    if (t < 128) us[t] = g_u[(b << 11) + r0 + t] * KK;
    __syncthreads();
    const float* Cb = g_C + ((size_t)b << 22) + ((size_t)r0 << 11) + j;
    float m = -3.0e38f, s0 = 0.0f, s1 = 0.0f, s2 = 0.0f, s3 = 0.0f;
    #pragma unroll 1
    for (int g = 0; g < 8; g++) {
        float c[16];
        #pragma unroll
        for (int q = 0; q < 16; q++) c[q] = Cb[(size_t)q << 11];
        Cb += (size_t)16 << 11;
        float x[16];
        #pragma unroll
        for (int q = 0; q < 16; q++) x[q] = fmaf(c[q], -KK, us[g * 16 + q]);
        float m01 = fmaxf(fmaxf(x[0], x[1]), fmaxf(x[2], x[3]));
        float m23 = fmaxf(fmaxf(x[4], x[5]), fmaxf(x[6], x[7]));
        float m45 = fmaxf(fmaxf(x[8], x[9]), fmaxf(x[10], x[11]));
        float m67 = fmaxf(fmaxf(x[12], x[13]), fmaxf(x[14], x[15]));
        float lm = fmaxf(fmaxf(m01, m23), fmaxf(m45, m67));
        float mn = fmaxf(m, lm);
        float sc = exp2f(m - mn);
        s0 *= sc; s1 *= sc; s2 *= sc; s3 *= sc;
        #pragma unroll
        for (int q = 0; q < 16; q += 4) {
            s0 += exp2f(x[q + 0] - mn);
            s1 += exp2f(x[q + 1] - mn);
            s2 += exp2f(x[q + 2] - mn);
            s3 += exp2f(x[q + 3] - mn);
        }
        m = mn;
    }
    float s = (s0 + s1) + (s2 + s3);
    int pidx = (((b << 4) + chunk) << 11) + j;
    g_pm[pidx] = m;
    g_ps[pidx] = s;
}

// ---- combine partials -> v; snapshot u,v for this iteration ---------------
__global__ __launch_bounds__(256) void k_combine(int b0, int it) {
    int idx = blockIdx.x * 256 + threadIdx.x;   // 0..8191
    int b = b0 + (idx >> 11), j = idx & 2047;
    int tg = (b << 11) + j;
    int base = (b << 4);
    float M = -3.0e38f;
    #pragma unroll
    for (int ch = 0; ch < 16; ch++)
        M = fmaxf(M, g_pm[((base + ch) << 11) + j]);
    float S = 0.0f;
    #pragma unroll
    for (int ch = 0; ch < 16; ch++)
        S = fmaf(g_ps[((base + ch) << 11) + j], exp2f(g_pm[((base + ch) << 11) + j] - M), S);
    float v = EPSI * g_lnu[tg] - EL2 * (M + __log2f(S));
    g_v[tg] = v;
    g_vsnap[it * NPb + tg] = v;
    g_usnap[it * NPb + tg] = g_u[tg];
}

// ---- pick stop iteration k* from errsum table -----------------------------
__global__ void k_pick() {
    if (threadIdx.x == 0) {
        int ks = NITER - 1;
        for (int it = 0; it < NITER; it++) {
            if (g_errsum[it] < 0.1f * NB) { ks = it; break; }
        }
        g_kstar = ks;
    }
}

// ---- final: out[b] = sum_ij exp((u+v-C)/eps)*C with snapshot k* -----------
__global__ __launch_bounds__(256) void k_final(float* __restrict__ out) {
    __shared__ float vs[2048];          // v * KK
    __shared__ float srw[8];
    int t = threadIdx.x, l = t & 31, w = t >> 5;
    int g = 4095 - blockIdx.x;
    int b = g >> 9;
    int ks = g_kstar;
    const float* ub = g_usnap + ks * NPb;
    const float4* vsrc = (const float4*)(g_vsnap + ks * NPb + (b << 11));
    #pragma unroll
    for (int q = 0; q < 2; q++) {
        float4 v4 = vsrc[t + q * 256];
        ((float4*)vs)[t + q * 256] = make_float4(v4.x * KK, v4.y * KK, v4.z * KK, v4.w * KK);
    }
    __syncthreads();
    int row4 = (g & 511) << 2;
    int bi = (b << 11) + row4 + (w >> 1);
    int half = w & 1;
    float uw = ub[bi] * KK;
    const float* Crow = g_C + ((size_t)bi << 11) + (half << 10);
    const float* vh = vs + (half << 10);
    float s0 = 0.0f, s1 = 0.0f, s2 = 0.0f, s3 = 0.0f;
    #pragma unroll
    for (int k = 0; k < 8; k++) {
        float4 c = *(const float4*)(Crow + k * 128 + l * 4);
        float4 vv = *(const float4*)(vh + k * 128 + l * 4);
        s0 = fmaf(exp2f(fmaf(c.x, -KK, uw + vv.x)), c.x, s0);
        s1 = fmaf(exp2f(fmaf(c.y, -KK, uw + vv.y)), c.y, s1);
        s2 = fmaf(exp2f(fmaf(c.z, -KK, uw + vv.z)), c.z, s2);
        s3 = fmaf(exp2f(fmaf(c.w, -KK, uw + vv.w)), c.w, s3);
    }
    float s = (s0 + s1) + (s2 + s3);
    #pragma unroll
    for (int off = 16; off; off >>= 1) s += __shfl_xor_sync(0xffffffffu, s, off);
    if (l == 0) srw[w] = s;
    __syncthreads();
    if (t == 0) {
        float e = 0.0f;
        #pragma unroll
        for (int q = 0; q < 8; q++) e += srw[q];
        atomicAdd(&out[b], e);
    }
}

extern "C" void kernel_launch(void* const* d_in, const int* in_sizes, int n_in,
                              void* d_out, int out_size) {
    const float* a = (const float*)d_in[0];
    const float* b = (const float*)d_in[1];
    float* out = (float*)d_out;
    k_prep<<<64, 256>>>(a, b, out);
    for (int grp = 0; grp < 2; grp++) {
        int b0 = 4 * grp;
        dim3 gg(16, 16, 4);
        k_gemm<<<gg, 256>>>(b0);
        k_weights<<<4, 256>>>(b0);
        for (int it = 0; it < NITER; it++) {
            k_row<<<4096, 256>>>(b0, it);
            k_col<<<512, 256>>>(b0);
            k_combine<<<32, 256>>>(b0, it);
        }
    }
    k_pick<<<1, 32>>>();
    k_final<<<4096, 256>>>(out);
}

// round 9
// speedup vs baseline: 1.4935x; 1.4935x over previous
#include <cuda_runtime.h>

#define NB 8
#define PP 2048
#define DD 64
#define EPSI 1e-3f
#define KK 1442.69504089f        /* 1000 * log2(e) */
#define EL2 6.9314718056e-4f     /* ln2 / 1000 */
#define NPb (NB*PP)
#define NITER 10
#define SMEM_FUSED (2*8*2048*4 + 2048*4 + 256)

__device__ __align__(256) float g_C[(size_t)NB * PP * PP]; // 134 MB cost matrix
__device__ __align__(256) float g_An[NPb * DD];
__device__ __align__(256) float g_Bn[NPb * DD];
__device__ __align__(256) float g_rs[NPb];
__device__ __align__(256) float g_cs[NPb];
__device__ __align__(256) float g_lmu[NPb];
__device__ __align__(256) float g_lnu[NPb];
__device__ __align__(256) float g_u[NPb];
__device__ __align__(256) float g_v[NPb];
__device__ __align__(256) float g_pT[NB * 64 * PP];   // col partial plain sums
__device__ float g_errsum[16];
__device__ int g_flag;

__device__ __forceinline__ void cp_async16(float* smem_dst, const float* gsrc) {
    unsigned sa = (unsigned)__cvta_generic_to_shared(smem_dst);
    asm volatile("cp.async.cg.shared.global [%0], [%1], 16;\n" :: "r"(sa), "l"(gsrc));
}

// ---------------- block sum reduction (256 threads) ------------------------
__device__ __forceinline__ float block_sum256(float v, float* red) {
    __syncthreads();
    #pragma unroll
    for (int off = 16; off; off >>= 1) v += __shfl_xor_sync(0xffffffffu, v, off);
    int w = threadIdx.x >> 5, l = threadIdx.x & 31;
    if (l == 0) red[w] = v;
    __syncthreads();
    if (threadIdx.x < 32) {
        float x = (l < 8) ? red[l] : 0.0f;
        #pragma unroll
        for (int off = 4; off; off >>= 1) x += __shfl_xor_sync(0xffffffffu, x, off);
        if (l == 0) red[32] = x;
    }
    __syncthreads();
    return red[32];
}

// ---------------- prep: normalize inputs, zero state -----------------------
__global__ __launch_bounds__(256) void k_prep(const float* __restrict__ a,
                                              const float* __restrict__ b,
                                              float* __restrict__ out) {
    int idx = blockIdx.x * 256 + threadIdx.x;          // 0..16383
    {
        const float4* s = (const float4*)(a + (size_t)idx * DD);
        float nrm = 0.0f;
        #pragma unroll
        for (int q = 0; q < 16; q++) {
            float4 t = s[q];
            nrm += t.x * t.x + t.y * t.y + t.z * t.z + t.w * t.w;
        }
        float sc = 1.0f / fmaxf(sqrtf(nrm), 1e-12f);
        float4* d = (float4*)(g_An + (size_t)idx * DD);
        #pragma unroll
        for (int q = 0; q < 16; q++) {
            float4 t = s[q];
            t.x *= sc; t.y *= sc; t.z *= sc; t.w *= sc;
            d[q] = t;
        }
    }
    {
        const float4* s = (const float4*)(b + (size_t)idx * DD);
        float nrm = 0.0f;
        #pragma unroll
        for (int q = 0; q < 16; q++) {
            float4 t = s[q];
            nrm += t.x * t.x + t.y * t.y + t.z * t.z + t.w * t.w;
        }
        float sc = 1.0f / fmaxf(sqrtf(nrm), 1e-12f);
        float4* d = (float4*)(g_Bn + (size_t)idx * DD);
        #pragma unroll
        for (int q = 0; q < 16; q++) {
            float4 t = s[q];
            t.x *= sc; t.y *= sc; t.z *= sc; t.w *= sc;
            d[q] = t;
        }
    }
    g_u[idx] = 0.0f; g_v[idx] = 0.0f; g_rs[idx] = 0.0f; g_cs[idx] = 0.0f;
    if (idx < NB) out[idx] = 0.0f;
    if (idx < 16) g_errsum[idx] = 0.0f;
    if (idx == 0) g_flag = 0;
}

// ---------------- GEMM: C = 1 - Ahat . Bhat^T, fused S row/col sums --------
__global__ __launch_bounds__(256) void k_gemm() {
    __shared__ float As[128][33];
    __shared__ float Bs[32][132];
    int b = blockIdx.z;
    int row0 = blockIdx.y * 128, col0 = blockIdx.x * 128;
    const float* Ab = g_An + (size_t)b * PP * DD;
    const float* Bb = g_Bn + (size_t)b * PP * DD;
    int t = threadIdx.x, tx = t & 15, ty = t >> 4;

    unsigned long long acc[8][4];
    #pragma unroll
    for (int i = 0; i < 8; i++)
        #pragma unroll
        for (int j = 0; j < 4; j++) acc[i][j] = 0ULL;

    #pragma unroll
    for (int kp = 0; kp < 2; kp++) {
        __syncthreads();
        int kq = t & 7, rq = t >> 3;
        #pragma unroll
        for (int p = 0; p < 4; p++) {
            int r = p * 32 + rq;
            float4 v = *(const float4*)(Ab + (size_t)(row0 + r) * DD + kp * 32 + kq * 4);
            As[r][kq * 4 + 0] = v.x; As[r][kq * 4 + 1] = v.y;
            As[r][kq * 4 + 2] = v.z; As[r][kq * 4 + 3] = v.w;
            float4 w = *(const float4*)(Bb + (size_t)(col0 + r) * DD + kp * 32 + kq * 4);
            Bs[kq * 4 + 0][r] = w.x; Bs[kq * 4 + 1][r] = w.y;
            Bs[kq * 4 + 2][r] = w.z; Bs[kq * 4 + 3][r] = w.w;
        }
        __syncthreads();
        #pragma unroll 4
        for (int k = 0; k < 32; k++) {
            union { float4 f; unsigned long long u[2]; } b0u, b1u;
            b0u.f = *(const float4*)&Bs[k][tx * 4];
            b1u.f = *(const float4*)&Bs[k][64 + tx * 4];
            #pragma unroll
            for (int i = 0; i < 8; i++) {
                unsigned int ai = __float_as_uint(As[ty * 8 + i][k]);
                unsigned long long a2;
                asm("mov.b64 %0, {%1, %1};" : "=l"(a2) : "r"(ai));
                asm("fma.rn.f32x2 %0, %1, %2, %0;" : "+l"(acc[i][0]) : "l"(a2), "l"(b0u.u[0]));
                asm("fma.rn.f32x2 %0, %1, %2, %0;" : "+l"(acc[i][1]) : "l"(a2), "l"(b0u.u[1]));
                asm("fma.rn.f32x2 %0, %1, %2, %0;" : "+l"(acc[i][2]) : "l"(a2), "l"(b1u.u[0]));
                asm("fma.rn.f32x2 %0, %1, %2, %0;" : "+l"(acc[i][3]) : "l"(a2), "l"(b1u.u[1]));
            }
        }
    }
    __syncthreads();

    float rs[8], cs8[8];
    #pragma unroll
    for (int j = 0; j < 8; j++) cs8[j] = 0.0f;
    #pragma unroll
    for (int i = 0; i < 8; i++) {
        float vals[8];
        #pragma unroll
        for (int jp = 0; jp < 4; jp++) {
            union { unsigned long long u; float2 f; } cv; cv.u = acc[i][jp];
            vals[jp * 2 + 0] = cv.f.x;
            vals[jp * 2 + 1] = cv.f.y;
        }
        size_t base = ((size_t)b * PP + row0 + ty * 8 + i) * (size_t)PP + col0;
        *(float4*)(g_C + base + tx * 4) =
            make_float4(1.0f - vals[0], 1.0f - vals[1], 1.0f - vals[2], 1.0f - vals[3]);
        *(float4*)(g_C + base + 64 + tx * 4) =
            make_float4(1.0f - vals[4], 1.0f - vals[5], 1.0f - vals[6], 1.0f - vals[7]);
        float rsum = 0.0f;
        #pragma unroll
        for (int j = 0; j < 8; j++) { rsum += vals[j]; cs8[j] += vals[j]; }
        rs[i] = rsum;
    }
    float* red = (float*)As;
    #pragma unroll
    for (int i = 0; i < 8; i++) red[(ty * 8 + i) * 16 + tx] = rs[i];
    __syncthreads();
    if (t < 128) {
        float s = 0.0f;
        #pragma unroll
        for (int q = 0; q < 16; q++) s += red[t * 16 + q];
        atomicAdd(&g_rs[b * PP + row0 + t], s);
    }
    __syncthreads();
    #pragma unroll
    for (int j = 0; j < 8; j++) {
        int cc = (j < 4) ? (tx * 4 + j) : (64 + tx * 4 + (j - 4));
        red[cc * 16 + ty] = cs8[j];
    }
    __syncthreads();
    if (t < 128) {
        float s = 0.0f;
        #pragma unroll
        for (int q = 0; q < 16; q++) s += red[t * 16 + q];
        atomicAdd(&g_cs[b * PP + col0 + t], s);
    }
}

// ---------------- weights -> log(mu+1e-8) ----------------------------------
__device__ __forceinline__ void wproc(const float* __restrict__ sum,
                                      float* __restrict__ out, float* red, int t) {
    float raw[8], s = 0.0f;
    #pragma unroll
    for (int q = 0; q < 8; q++) {
        raw[q] = sum[t + 256 * q] * (1.0f / PP);
        s += fabsf(raw[q]);
    }
    s = block_sum256(s, red);
    float inv1 = 1.0f / fmaxf(s, 1e-12f);
    float c[8]; float s2 = 0.0f;
    #pragma unroll
    for (int q = 0; q < 8; q++) { c[q] = fmaxf(raw[q] * inv1, 0.0f); s2 += fabsf(c[q]); }
    s2 = block_sum256(s2, red);
    float inv2 = 1.0f / fmaxf(s2, 1e-12f);
    #pragma unroll
    for (int q = 0; q < 8; q++) out[t + 256 * q] = logf(c[q] * inv2 + 1e-8f);
}

__global__ __launch_bounds__(256) void k_weights() {
    __shared__ float red[40];
    int b = blockIdx.x, t = threadIdx.x;
    wproc(g_rs + b * PP, g_lmu + b * PP, red, t);
    wproc(g_cs + b * PP, g_lnu + b * PP, red, t);
}

// ---- FUSED iteration: 32-row chunk, cp.async ring, one C read per iter ----
// phase1 (warp-per-row): x=(v-C)K stored; M,S; u_new; w_r=exp2(u_newK+M).
// phase2: T_j += e_rj * w_r (no exp). v from T in k_combine.
__global__ __launch_bounds__(256) void k_fused(int it, int dir) {
    if (g_flag) return;
    extern __shared__ float sm[];
    float* buf = sm;                 // [2][8][2048]
    float* vs  = sm + 2 * 8 * 2048;  // [2048] v*KK
    float* wsh = vs + 2048;          // [8]
    int t = threadIdx.x, l = t & 31, w = t >> 5;
    int gid = dir ? (511 - blockIdx.x) : blockIdx.x;
    int b = gid >> 6, chunk = gid & 63;
    int rowbase = (b << 11) + (chunk << 5);
    const float* Cbase = g_C + ((size_t)rowbase << 11);

    // stage v*KK (2048 floats)
    {
        const float4* vsrc = (const float4*)(g_v + (b << 11));
        #pragma unroll
        for (int q = 0; q < 2; q++) {
            float4 v4 = vsrc[t + q * 256];
            ((float4*)vs)[t + q * 256] =
                make_float4(v4.x * KK, v4.y * KK, v4.z * KK, v4.w * KK);
        }
    }
    // issue half 0
    {
        const float* src = Cbase;
        float* dst = buf;
        #pragma unroll
        for (int k = 0; k < 16; k++) {
            int f4 = k * 256 + t;
            cp_async16(dst + f4 * 4, src + f4 * 4);
        }
        asm volatile("cp.async.commit_group;\n");
    }

    float erracc = 0.0f;
    float T[8];
    #pragma unroll
    for (int k = 0; k < 8; k++) T[k] = 0.0f;

    #pragma unroll 1
    for (int h = 0; h < 4; h++) {
        if (h < 3) {
            const float* src = Cbase + (h + 1) * 16384;
            float* dst = buf + ((h + 1) & 1) * 16384;
            #pragma unroll
            for (int k = 0; k < 16; k++) {
                int f4 = k * 256 + t;
                cp_async16(dst + f4 * 4, src + f4 * 4);
            }
            asm volatile("cp.async.commit_group;\n");
            asm volatile("cp.async.wait_group 1;\n");
        } else {
            asm volatile("cp.async.wait_group 0;\n");
        }
        __syncthreads();
        // phase 1: warp w owns local row w of this half
        float* rowp = buf + (h & 1) * 16384 + w * 2048;
        float M = -3.0e38f;
        #pragma unroll
        for (int k = 0; k < 16; k++) {
            float4 c = *(float4*)(rowp + l * 4 + k * 128);
            float4 vv = *(const float4*)(vs + l * 4 + k * 128);
            float4 x;
            x.x = fmaf(c.x, -KK, vv.x);
            x.y = fmaf(c.y, -KK, vv.y);
            x.z = fmaf(c.z, -KK, vv.z);
            x.w = fmaf(c.w, -KK, vv.w);
            *(float4*)(rowp + l * 4 + k * 128) = x;
            M = fmaxf(M, fmaxf(fmaxf(x.x, x.y), fmaxf(x.z, x.w)));
        }
        #pragma unroll
        for (int off = 16; off; off >>= 1)
            M = fmaxf(M, __shfl_xor_sync(0xffffffffu, M, off));
        float s0 = 0.0f, s1 = 0.0f, s2 = 0.0f, s3 = 0.0f;
        #pragma unroll
        for (int k = 0; k < 16; k++) {
            float4 x = *(float4*)(rowp + l * 4 + k * 128);
            float4 e;
            e.x = exp2f(x.x - M);
            e.y = exp2f(x.y - M);
            e.z = exp2f(x.z - M);
            e.w = exp2f(x.w - M);
            *(float4*)(rowp + l * 4 + k * 128) = e;
            s0 += e.x; s1 += e.y; s2 += e.z; s3 += e.w;
        }
        float S = (s0 + s1) + (s2 + s3);
        #pragma unroll
        for (int off = 16; off; off >>= 1)
            S += __shfl_xor_sync(0xffffffffu, S, off);
        if (l == 0) {
            int gr = rowbase + h * 8 + w;
            float un = EPSI * g_lmu[gr] - EL2 * (M + __log2f(S));
            erracc += fabsf(un - g_u[gr]);
            g_u[gr] = un;
            wsh[w] = exp2f(fmaf(un, KK, M));   // = exp2(1.44*lmu - log2 S), bounded
        }
        __syncthreads();
        // phase 2: per-thread columns, T += e * w_r
        float wr[8];
        #pragma unroll
        for (int r = 0; r < 8; r++) wr[r] = wsh[r];
        const float* bb = buf + (h & 1) * 16384;
        #pragma unroll
        for (int k = 0; k < 8; k++) {
            int j = (w << 8) + l + (k << 5);
            float acc = T[k];
            #pragma unroll
            for (int r = 0; r < 8; r++)
                acc = fmaf(bb[r * 2048 + j], wr[r], acc);
            T[k] = acc;
        }
        __syncthreads();   // buffer free before next issue targets it
    }
    int cidx = ((b << 6) + chunk) << 11;
    #pragma unroll
    for (int k = 0; k < 8; k++)
        g_pT[cidx + (w << 8) + l + (k << 5)] = T[k];
    if (l == 0) atomicAdd(&g_errsum[it], erracc);
}

// ---- combine T partials -> v; early-stop flag -----------------------------
__global__ __launch_bounds__(256) void k_combine(int it) {
    if (g_flag) return;
    int idx = blockIdx.x * 256 + threadIdx.x;   // 16384 = b*2048 + j
    int b = idx >> 11, j = idx & 2047;
    int base = b << 6;
    float T = 0.0f;
    #pragma unroll 8
    for (int ch = 0; ch < 64; ch++)
        T += g_pT[((base + ch) << 11) + j];
    float vk_old = g_v[idx] * KK;
    g_v[idx] = EPSI * g_lnu[idx] - EL2 * (__log2f(T) - vk_old);
    if (idx == 0 && g_errsum[it] < 0.1f * NB) g_flag = 1;
}

// ---- final (REVERSE sweep): out[b] = sum_ij exp((u+v-C)/eps)*C ------------
__global__ __launch_bounds__(256) void k_final(float* __restrict__ out) {
    __shared__ float vsm[2048];          // v * KK
    __shared__ float srw[8];
    int t = threadIdx.x, l = t & 31, w = t >> 5;
    int g = 4095 - blockIdx.x;
    int b = g >> 9;
    const float4* vsrc = (const float4*)(g_v + (b << 11));
    #pragma unroll
    for (int q = 0; q < 2; q++) {
        float4 v4 = vsrc[t + q * 256];
        ((float4*)vsm)[t + q * 256] = make_float4(v4.x * KK, v4.y * KK, v4.z * KK, v4.w * KK);
    }
    __syncthreads();
    int row4 = (g & 511) << 2;
    int bi = (b << 11) + row4 + (w >> 1);
    int half = w & 1;
    float uw = g_u[bi] * KK;
    const float* Crow = g_C + ((size_t)bi << 11) + (half << 10);
    const float* vh = vsm + (half << 10);
    float s0 = 0.0f, s1 = 0.0f, s2 = 0.0f, s3 = 0.0f;
    #pragma unroll
    for (int k = 0; k < 8; k++) {
        float4 c = *(const float4*)(Crow + k * 128 + l * 4);
        float4 vv = *(const float4*)(vh + k * 128 + l * 4);
        s0 = fmaf(exp2f(fmaf(c.x, -KK, uw + vv.x)), c.x, s0);
        s1 = fmaf(exp2f(fmaf(c.y, -KK, uw + vv.y)), c.y, s1);
        s2 = fmaf(exp2f(fmaf(c.z, -KK, uw + vv.z)), c.z, s2);
        s3 = fmaf(exp2f(fmaf(c.w, -KK, uw + vv.w)), c.w, s3);
    }
    float s = (s0 + s1) + (s2 + s3);
    #pragma unroll
    for (int off = 16; off; off >>= 1) s += __shfl_xor_sync(0xffffffffu, s, off);
    if (l == 0) srw[w] = s;
    __syncthreads();
    if (t == 0) {
        float e = 0.0f;
        #pragma unroll
        for (int q = 0; q < 8; q++) e += srw[q];
        atomicAdd(&out[b], e);
    }
}

extern "C" void kernel_launch(void* const* d_in, const int* in_sizes, int n_in,
                              void* d_out, int out_size) {
    const float* a = (const float*)d_in[0];
    const float* b = (const float*)d_in[1];
    float* out = (float*)d_out;
    cudaFuncSetAttribute(k_fused, cudaFuncAttributeMaxDynamicSharedMemorySize,
                         SMEM_FUSED);
    k_prep<<<64, 256>>>(a, b, out);
    dim3 gg(16, 16, NB);
    k_gemm<<<gg, 256>>>();
    k_weights<<<NB, 256>>>();
    for (int it = 0; it < NITER; it++) {
        k_fused<<<512, 256, SMEM_FUSED>>>(it, (it & 1) ^ 1);
        k_combine<<<64, 256>>>(it);
    }
    k_final<<<4096, 256>>>(out);
}